// round 7
// baseline (speedup 1.0000x reference)
#include <cuda_runtime.h>
#include <cuda_bf16.h>
#include <cstdint>

#define DD 2048
#define BB 256
#define TT 64

// scratch (static device arrays — no allocations)
__device__ float          g_u [BB * DD];   // 2 MB: u = E@(W-I) + E + hb
__device__ __nv_bfloat16  g_Eh[BB * DD];   // 1 MB: bf16(E)

// ---------------------------------------------------------------------------
// convE: E -> bf16. 512 blocks x 128 threads, one 8-float pair per thread.
// ---------------------------------------------------------------------------
__global__ __launch_bounds__(128) void convE_kernel(const float* __restrict__ E)
{
    const int j = blockIdx.x * 128 + threadIdx.x;   // 65536 jobs
    float4 a = reinterpret_cast<const float4*>(E)[j * 2];
    float4 b = reinterpret_cast<const float4*>(E)[j * 2 + 1];
    __nv_bfloat162 p0 = __floats2bfloat162_rn(a.x, a.y);
    __nv_bfloat162 p1 = __floats2bfloat162_rn(a.z, a.w);
    __nv_bfloat162 p2 = __floats2bfloat162_rn(b.x, b.y);
    __nv_bfloat162 p3 = __floats2bfloat162_rn(b.z, b.w);
    uint4 o;
    o.x = *reinterpret_cast<uint32_t*>(&p0);
    o.y = *reinterpret_cast<uint32_t*>(&p1);
    o.z = *reinterpret_cast<uint32_t*>(&p2);
    o.w = *reinterpret_cast<uint32_t*>(&p3);
    reinterpret_cast<uint4*>(g_Eh)[j] = o;
}

// ---------------------------------------------------------------------------
// helpers
// ---------------------------------------------------------------------------
__device__ __forceinline__ void mma16816(float* d, const uint32_t* a,
                                         uint32_t b0, uint32_t b1)
{
    asm volatile(
        "mma.sync.aligned.m16n8k16.row.col.f32.bf16.bf16.f32 "
        "{%0,%1,%2,%3}, {%4,%5,%6,%7}, {%8,%9}, {%0,%1,%2,%3};\n"
        : "+f"(d[0]), "+f"(d[1]), "+f"(d[2]), "+f"(d[3])
        : "r"(a[0]), "r"(a[1]), "r"(a[2]), "r"(a[3]), "r"(b0), "r"(b1));
}
__device__ __forceinline__ void ldsm_x4(uint32_t* r, uint32_t addr)
{
    asm volatile("ldmatrix.sync.aligned.m8n8.x4.shared.b16 {%0,%1,%2,%3}, [%4];\n"
                 : "=r"(r[0]), "=r"(r[1]), "=r"(r[2]), "=r"(r[3]) : "r"(addr));
}
__device__ __forceinline__ void ldsm_x4_t(uint32_t* r, uint32_t addr)
{
    asm volatile("ldmatrix.sync.aligned.m8n8.x4.trans.shared.b16 {%0,%1,%2,%3}, [%4];\n"
                 : "=r"(r[0]), "=r"(r[1]), "=r"(r[2]), "=r"(r[3]) : "r"(addr));
}
__device__ __forceinline__ void cp16(uint32_t saddr, const void* gaddr)
{
    asm volatile("cp.async.cg.shared.global [%0], [%1], 16;\n"
                 :: "r"(saddr), "l"(gaddr) : "memory");
}
__device__ __forceinline__ void lds128f(float4& v, uint32_t addr)
{
    asm volatile("ld.shared.v4.f32 {%0,%1,%2,%3}, [%4];\n"
                 : "=f"(v.x), "=f"(v.y), "=f"(v.z), "=f"(v.w) : "r"(addr));
}
__device__ __forceinline__ void sts128(uint32_t addr, const uint4& o)
{
    asm volatile("st.shared.v4.b32 [%0], {%1,%2,%3,%4};\n"
                 :: "r"(addr), "r"(o.x), "r"(o.y), "r"(o.z), "r"(o.w));
}
__device__ __forceinline__ uint4 pack_bf16x8(const float4& a, const float4& b)
{
    __nv_bfloat162 p0 = __floats2bfloat162_rn(a.x, a.y);
    __nv_bfloat162 p1 = __floats2bfloat162_rn(a.z, a.w);
    __nv_bfloat162 p2 = __floats2bfloat162_rn(b.x, b.y);
    __nv_bfloat162 p3 = __floats2bfloat162_rn(b.z, b.w);
    uint4 o;
    o.x = *reinterpret_cast<uint32_t*>(&p0);
    o.y = *reinterpret_cast<uint32_t*>(&p1);
    o.z = *reinterpret_cast<uint32_t*>(&p2);
    o.w = *reinterpret_cast<uint32_t*>(&p3);
    return o;
}

// ---------------------------------------------------------------------------
// Fused GEMM: U = bf16(E) @ bf16(W - I) + E + hb
// 3-stage cp.async ring: A bf16 (swizzled) + B fp32 (linear 64x64) in the SAME
// commit group; wait_group 1 keeps 2 stages in flight. Converted bf16 B is
// double-buffered. Per iter: wait(it); bar1; issue(it+2); convert(it); bar2; mma.
// smem: As 3x8K | Bs 2x8K | F 3x16K = 88 KB dynamic
// ---------------------------------------------------------------------------
__global__ __launch_bounds__(256) void gemm_u_kernel(
    const float* __restrict__ E, const float* __restrict__ W,
    const float* __restrict__ hb)
{
    extern __shared__ __align__(1024) char smem[];
    const uint32_t base = (uint32_t)__cvta_generic_to_shared(smem);
    // As[s] = base + s*8192         (s = 0..2)
    // Bs[p] = base + 24576 + p*8192 (p = 0..1)
    // F[s]  = base + 40960 + s*16384

    const int tid  = threadIdx.x;
    const int lane = tid & 31;
    const int wid  = tid >> 5;
    const int wm   = (wid >> 2) << 5;
    const int wn   = (wid & 3) << 4;
    const int bm   = blockIdx.y << 6;
    const int bn   = blockIdx.x << 6;

    float acc[2][2][4];
    #pragma unroll
    for (int i = 0; i < 2; i++)
        #pragma unroll
        for (int j = 0; j < 2; j++)
            #pragma unroll
            for (int k = 0; k < 4; k++) acc[i][j][k] = 0.f;

    const int rA = tid >> 3;            // 0..31 (+32)
    const int cA = tid & 7;
    const uint32_t swz0 = (uint32_t)((rA << 7) + ((cA ^ (rA & 7)) << 4));
    const uint32_t swz1 = swz0 + (32 << 7);

    const __nv_bfloat16* gA0 = g_Eh + (size_t)(bm + rA) * DD + cA * 8;
    const __nv_bfloat16* gA1 = gA0 + (size_t)32 * DD;
    const float* gW = W + bn;

    // ldmatrix addressing (proven scheme)
    const int l15 = lane & 15;
    const int l7  = lane & 7;
    const int kcB = lane >> 4;
    uint32_t aRow[2];
    #pragma unroll
    for (int im = 0; im < 2; im++) aRow[im] = (uint32_t)((wm + im * 16 + l15) << 7);
    const int nChunkBase = wn >> 3;

    #define ISSUE(st_)                                                      \
        {                                                                   \
            const int st = (st_);                                           \
            const uint32_t sa = base + (uint32_t)((st % 3) * 8192);         \
            const uint32_t sf = base + 40960u + (uint32_t)((st % 3) * 16384); \
            const int k0 = st * 64;                                         \
            cp16(sa + swz0, gA0 + k0);                                      \
            cp16(sa + swz1, gA1 + k0);                                      \
            _Pragma("unroll")                                               \
            for (int j = 0; j < 4; j++) {                                   \
                const int c = tid + 256 * j;                                \
                cp16(sf + (uint32_t)(c * 16),                               \
                     gW + (size_t)(k0 + (c >> 4)) * DD + (c & 15) * 4);     \
            }                                                               \
            asm volatile("cp.async.commit_group;\n" ::: "memory");          \
        }

    ISSUE(0);
    ISSUE(1);

    const int NIT = DD / 64;   // 32
    for (int it = 0; it < NIT; it++) {
        if (it == NIT - 1)
            asm volatile("cp.async.wait_group 0;\n" ::: "memory");
        else
            asm volatile("cp.async.wait_group 1;\n" ::: "memory");
        __syncthreads();                               // bar1

        if (it + 2 < NIT) ISSUE(it + 2);

        // convert B fp32 -> bf16 (diag fix), swizzled STS into Bs[it&1]
        const uint32_t sf  = base + 40960u + (uint32_t)((it % 3) * 16384);
        const uint32_t sbs = base + 24576u + (uint32_t)((it & 1) * 8192);
        {
            float4 f0a, f0b, f1a, f1b;
            const uint32_t i0 = sf + (uint32_t)(rA * 256 + cA * 32);
            lds128f(f0a, i0);
            lds128f(f0b, i0 + 16);
            lds128f(f1a, i0 + 32 * 256);
            lds128f(f1b, i0 + 32 * 256 + 16);
            const int d0 = (it * 64 + rA) - (bn + cA * 8);
            if (d0 >= 0 && d0 < 4)      reinterpret_cast<float*>(&f0a)[d0]     -= 1.0f;
            else if (d0 >= 4 && d0 < 8) reinterpret_cast<float*>(&f0b)[d0 - 4] -= 1.0f;
            const int d1 = d0 + 32;
            if (d1 >= 0 && d1 < 4)      reinterpret_cast<float*>(&f1a)[d1]     -= 1.0f;
            else if (d1 >= 4 && d1 < 8) reinterpret_cast<float*>(&f1b)[d1 - 4] -= 1.0f;
            sts128(sbs + swz0, pack_bf16x8(f0a, f0b));
            sts128(sbs + swz1, pack_bf16x8(f1a, f1b));
        }
        __syncthreads();                               // bar2

        const uint32_t sAc = base + (uint32_t)((it % 3) * 8192);
        #pragma unroll
        for (int kk = 0; kk < 4; kk++) {
            uint32_t a[2][4], b[4];
            const int kchunk = kk * 2 + kcB;
            #pragma unroll
            for (int im = 0; im < 2; im++)
                ldsm_x4(a[im], sAc + aRow[im] + (uint32_t)((kchunk ^ l7) << 4));
            {
                const int krow = kk * 16 + l15;
                const int nchunk = nChunkBase + kcB;
                ldsm_x4_t(b, sbs + (uint32_t)(krow << 7)
                               + (uint32_t)((nchunk ^ (krow & 7)) << 4));
            }
            #pragma unroll
            for (int im = 0; im < 2; im++) {
                mma16816(acc[im][0], a[im], b[0], b[1]);
                mma16816(acc[im][1], a[im], b[2], b[3]);
            }
        }
    }
    #undef ISSUE

    // epilogue: u = acc + E (exact identity) + hb
    #pragma unroll
    for (int im = 0; im < 2; im++) {
        const int row0e = bm + wm + im * 16 + (lane >> 2);
        #pragma unroll
        for (int in = 0; in < 2; in++) {
            const int col = bn + wn + in * 8 + ((lane & 3) << 1);
            const float h0 = hb[col], h1 = hb[col + 1];
            g_u[(size_t)row0e * DD + col]
                = acc[im][in][0] + E[(size_t)row0e * DD + col] + h0;
            g_u[(size_t)row0e * DD + col + 1]
                = acc[im][in][1] + E[(size_t)row0e * DD + col + 1] + h1;
            g_u[(size_t)(row0e + 8) * DD + col]
                = acc[im][in][2] + E[(size_t)(row0e + 8) * DD + col] + h0;
            g_u[(size_t)(row0e + 8) * DD + col + 1]
                = acc[im][in][3] + E[(size_t)(row0e + 8) * DD + col + 1] + h1;
        }
    }
}

// ---------------------------------------------------------------------------
// Kernel B: scoring (round-3 proven register version; unroll 8).
// grid (256, 2), 512 threads; warp -> 2 rows, __ldcs on theo stream.
// ---------------------------------------------------------------------------
__global__ __launch_bounds__(512) void score_kernel(
    const float* __restrict__ E,
    const float* __restrict__ theo,
    const float* __restrict__ cand,
    const float* __restrict__ vb,
    float* __restrict__ out)
{
    const int b    = blockIdx.x;
    const int tc   = blockIdx.y;       // 0..1
    const int tid  = threadIdx.x;
    const int lane = tid & 31;
    const int wid  = tid >> 5;         // 0..15

    __shared__ float u_s[DD];
    __shared__ float red[32];
    __shared__ float s_vb, s_pos;

    float pv, pp = 0.f;
    {
        const int i = tid * 4;
        float4 u4 = *reinterpret_cast<const float4*>(&g_u[(size_t)b * DD + i]);
        *reinterpret_cast<float4*>(&u_s[i]) = u4;
        float4 e4 = *reinterpret_cast<const float4*>(&E[(size_t)b * DD + i]);
        float4 v4 = *reinterpret_cast<const float4*>(&vb[i]);
        pv = e4.x * v4.x + e4.y * v4.y + e4.z * v4.z + e4.w * v4.w;
        if (tc == 0) {
            float4 c4 = *reinterpret_cast<const float4*>(&cand[(size_t)b * DD + i]);
            pp = u4.x * c4.x + u4.y * c4.y + u4.z * c4.z + u4.w * c4.w;
        }
    }
    #pragma unroll
    for (int o = 16; o > 0; o >>= 1) {
        pv += __shfl_xor_sync(0xFFFFFFFFu, pv, o);
        pp += __shfl_xor_sync(0xFFFFFFFFu, pp, o);
    }
    if (lane == 0) { red[wid] = pv; red[16 + wid] = pp; }
    __syncthreads();
    if (tid == 0) {
        float v = 0.f, p = 0.f;
        #pragma unroll
        for (int w = 0; w < 16; w++) { v += red[w]; p += red[16 + w]; }
        s_vb  = v;
        s_pos = p + v;
    }
    __syncthreads();
    const float vbb = s_vb;

    const int t0 = tc * 32 + wid * 2;
    const float4* ra  = reinterpret_cast<const float4*>(&theo[((size_t)b * TT + t0) * DD]);
    const float4* rb  = ra + DD / 4;
    const float4* u4p = reinterpret_cast<const float4*>(u_s);

    float s0 = 0.f, s1 = 0.f;
    #pragma unroll 8
    for (int i = lane; i < DD / 4; i += 32) {
        float4 x = __ldcs(&ra[i]);
        float4 y = __ldcs(&rb[i]);
        float4 u = u4p[i];
        s0 += x.x * u.x + x.y * u.y + x.z * u.z + x.w * u.w;
        s1 += y.x * u.x + y.y * u.y + y.z * u.z + y.w * u.w;
    }
    #pragma unroll
    for (int o = 16; o > 0; o >>= 1) {
        s0 += __shfl_xor_sync(0xFFFFFFFFu, s0, o);
        s1 += __shfl_xor_sync(0xFFFFFFFFu, s1, o);
    }
    if (lane == 0) {
        out[b * (TT + 1) + 1 + t0]     = s0 + vbb;
        out[b * (TT + 1) + 1 + t0 + 1] = s1 + vbb;
    }
    if (tc == 0 && tid == 0) out[b * (TT + 1)] = s_pos;
}

// ---------------------------------------------------------------------------
// launch: 0=experimental [B,D], 1=theoretical [B,T,D], 2=candidate [B,D],
//         3=W [D,D], 4=vb [D], 5=hb [D] ; out fp32 [B, 1+T]
// ---------------------------------------------------------------------------
extern "C" void kernel_launch(void* const* d_in, const int* in_sizes, int n_in,
                              void* d_out, int out_size)
{
    const float* E    = (const float*)d_in[0];
    const float* theo = (const float*)d_in[1];
    const float* cand = (const float*)d_in[2];
    const float* W    = (const float*)d_in[3];
    const float* vb   = (const float*)d_in[4];
    const float* hb   = (const float*)d_in[5];
    float*       out  = (float*)d_out;

    const int SMEM = 24576 + 16384 + 3 * 16384;   // 90112 B
    cudaFuncSetAttribute(gemm_u_kernel,
                         cudaFuncAttributeMaxDynamicSharedMemorySize, SMEM);

    convE_kernel<<<512, 128>>>(E);
    gemm_u_kernel<<<dim3(DD / 64, BB / 64), 256, SMEM>>>(E, W, hb);
    score_kernel<<<dim3(BB, 2), 512>>>(E, theo, cand, vb, out);
}

// round 8
// speedup vs baseline: 1.3343x; 1.3343x over previous
#include <cuda_runtime.h>
#include <cuda_bf16.h>
#include <cstdint>

#define DD 2048
#define BB 256
#define TT 64

// scratch (static device arrays — no allocations)
__device__ float          g_u [BB * DD];   // 2 MB: u = E@(W-I) + E + hb
__device__ __nv_bfloat16  g_Eh[BB * DD];   // 1 MB
__device__ __nv_bfloat16  g_Wh[DD * DD];   // 8 MB: bf16(W - I)

// ---------------------------------------------------------------------------
// Kernel 0: convert (round-6 proven). 1 thread = 2 float4 -> one uint4 store.
// ---------------------------------------------------------------------------
__global__ __launch_bounds__(256) void convert_kernel(
    const float* __restrict__ E, const float* __restrict__ W)
{
    const int NWP = DD * DD / 8;              // 524288 W pairs
    const int j = blockIdx.x * 256 + threadIdx.x;
    if (j < NWP) {
        float4 a = reinterpret_cast<const float4*>(W)[j * 2];
        float4 b = reinterpret_cast<const float4*>(W)[j * 2 + 1];
        const int fbase = j * 8;
        const int r = fbase >> 11;
        const int d = r - (fbase & (DD - 1));
        if (d >= 0 && d < 4)      reinterpret_cast<float*>(&a)[d]     -= 1.0f;
        else if (d >= 4 && d < 8) reinterpret_cast<float*>(&b)[d - 4] -= 1.0f;
        __nv_bfloat162 p0 = __floats2bfloat162_rn(a.x, a.y);
        __nv_bfloat162 p1 = __floats2bfloat162_rn(a.z, a.w);
        __nv_bfloat162 p2 = __floats2bfloat162_rn(b.x, b.y);
        __nv_bfloat162 p3 = __floats2bfloat162_rn(b.z, b.w);
        uint4 o;
        o.x = *reinterpret_cast<uint32_t*>(&p0);
        o.y = *reinterpret_cast<uint32_t*>(&p1);
        o.z = *reinterpret_cast<uint32_t*>(&p2);
        o.w = *reinterpret_cast<uint32_t*>(&p3);
        reinterpret_cast<uint4*>(g_Wh)[j] = o;
    } else {
        const int k = j - NWP;
        float4 a = reinterpret_cast<const float4*>(E)[k * 2];
        float4 b = reinterpret_cast<const float4*>(E)[k * 2 + 1];
        __nv_bfloat162 p0 = __floats2bfloat162_rn(a.x, a.y);
        __nv_bfloat162 p1 = __floats2bfloat162_rn(a.z, a.w);
        __nv_bfloat162 p2 = __floats2bfloat162_rn(b.x, b.y);
        __nv_bfloat162 p3 = __floats2bfloat162_rn(b.z, b.w);
        uint4 o;
        o.x = *reinterpret_cast<uint32_t*>(&p0);
        o.y = *reinterpret_cast<uint32_t*>(&p1);
        o.z = *reinterpret_cast<uint32_t*>(&p2);
        o.w = *reinterpret_cast<uint32_t*>(&p3);
        reinterpret_cast<uint4*>(g_Eh)[k] = o;
    }
}

// ---------------------------------------------------------------------------
// Kernel A: tensor-core GEMM  U = Eh @ Wh + E + hb  (round-3 proven, verbatim)
// ---------------------------------------------------------------------------
__device__ __forceinline__ void mma16816(float* d, const uint32_t* a,
                                         uint32_t b0, uint32_t b1)
{
    asm volatile(
        "mma.sync.aligned.m16n8k16.row.col.f32.bf16.bf16.f32 "
        "{%0,%1,%2,%3}, {%4,%5,%6,%7}, {%8,%9}, {%0,%1,%2,%3};\n"
        : "+f"(d[0]), "+f"(d[1]), "+f"(d[2]), "+f"(d[3])
        : "r"(a[0]), "r"(a[1]), "r"(a[2]), "r"(a[3]), "r"(b0), "r"(b1));
}
__device__ __forceinline__ void ldsm_x4(uint32_t* r, uint32_t addr)
{
    asm volatile("ldmatrix.sync.aligned.m8n8.x4.shared.b16 {%0,%1,%2,%3}, [%4];\n"
                 : "=r"(r[0]), "=r"(r[1]), "=r"(r[2]), "=r"(r[3]) : "r"(addr));
}
__device__ __forceinline__ void ldsm_x4_t(uint32_t* r, uint32_t addr)
{
    asm volatile("ldmatrix.sync.aligned.m8n8.x4.trans.shared.b16 {%0,%1,%2,%3}, [%4];\n"
                 : "=r"(r[0]), "=r"(r[1]), "=r"(r[2]), "=r"(r[3]) : "r"(addr));
}
__device__ __forceinline__ void cp16(uint32_t saddr, const void* gaddr)
{
    asm volatile("cp.async.cg.shared.global [%0], [%1], 16;\n"
                 :: "r"(saddr), "l"(gaddr) : "memory");
}

__global__ __launch_bounds__(256) void gemm_u_kernel(
    const float* __restrict__ E, const float* __restrict__ hb)
{
    __shared__ __align__(1024) __nv_bfloat16 As[2][64 * 64];
    __shared__ __align__(1024) __nv_bfloat16 Bs[2][64 * 64];

    const int tid  = threadIdx.x;
    const int lane = tid & 31;
    const int wid  = tid >> 5;
    const int wm   = (wid >> 2) << 5;
    const int wn   = (wid & 3) << 4;
    const int bm   = blockIdx.y << 6;
    const int bn   = blockIdx.x << 6;

    float acc[2][2][4];
    #pragma unroll
    for (int i = 0; i < 2; i++)
        #pragma unroll
        for (int j = 0; j < 2; j++)
            #pragma unroll
            for (int k = 0; k < 4; k++) acc[i][j][k] = 0.f;

    const int r0 = tid >> 3;
    const int c0 = tid & 7;
    const uint32_t swzOff  = (uint32_t)((r0 << 7) + ((c0 ^ (r0 & 7)) << 4));
    const uint32_t swzOff2 = swzOff + (32 << 7);

    uint32_t sA[2], sB[2];
    sA[0] = (uint32_t)__cvta_generic_to_shared(&As[0][0]);
    sA[1] = (uint32_t)__cvta_generic_to_shared(&As[1][0]);
    sB[0] = (uint32_t)__cvta_generic_to_shared(&Bs[0][0]);
    sB[1] = (uint32_t)__cvta_generic_to_shared(&Bs[1][0]);

    const __nv_bfloat16* gA  = g_Eh + (size_t)(bm + r0) * DD + c0 * 8;
    const __nv_bfloat16* gA2 = gA + (size_t)32 * DD;
    const __nv_bfloat16* gB  = g_Wh + (size_t)r0 * DD + bn + c0 * 8;
    const __nv_bfloat16* gB2 = gB + (size_t)32 * DD;

    const int l15 = lane & 15;
    const int l7  = lane & 7;
    const int kcB = lane >> 4;
    uint32_t aRow[2];
    #pragma unroll
    for (int im = 0; im < 2; im++) aRow[im] = (uint32_t)((wm + im * 16 + l15) << 7);
    const int nChunkBase = wn >> 3;

    #define LOAD_TILES(s, k0)                                              \
        {                                                                  \
            cp16(sA[s] + swzOff,  gA  + (k0));                             \
            cp16(sA[s] + swzOff2, gA2 + (k0));                             \
            cp16(sB[s] + swzOff,  gB  + (size_t)(k0) * DD);                \
            cp16(sB[s] + swzOff2, gB2 + (size_t)(k0) * DD);                \
            asm volatile("cp.async.commit_group;\n" ::: "memory");         \
        }

    LOAD_TILES(0, 0);

    const int NIT = DD / 64;
    for (int it = 0; it < NIT; it++) {
        const int s = it & 1;
        if (it + 1 < NIT) {
            LOAD_TILES(s ^ 1, (it + 1) * 64);
            asm volatile("cp.async.wait_group 1;\n" ::: "memory");
        } else {
            asm volatile("cp.async.wait_group 0;\n" ::: "memory");
        }
        __syncthreads();

        #pragma unroll
        for (int kk = 0; kk < 4; kk++) {
            uint32_t a[2][4], b[4];
            const int kchunk = kk * 2 + kcB;
            #pragma unroll
            for (int im = 0; im < 2; im++)
                ldsm_x4(a[im], sA[s] + aRow[im] + (uint32_t)((kchunk ^ l7) << 4));
            {
                const int krow = kk * 16 + l15;
                const int nchunk = nChunkBase + kcB;
                ldsm_x4_t(b, sB[s] + (uint32_t)(krow << 7)
                               + (uint32_t)((nchunk ^ (krow & 7)) << 4));
            }
            #pragma unroll
            for (int im = 0; im < 2; im++) {
                mma16816(acc[im][0], a[im], b[0], b[1]);
                mma16816(acc[im][1], a[im], b[2], b[3]);
            }
        }
        __syncthreads();
    }
    #undef LOAD_TILES

    #pragma unroll
    for (int im = 0; im < 2; im++) {
        const int row0e = bm + wm + im * 16 + (lane >> 2);
        #pragma unroll
        for (int in = 0; in < 2; in++) {
            const int col = bn + wn + in * 8 + ((lane & 3) << 1);
            const float h0 = hb[col], h1 = hb[col + 1];
            g_u[(size_t)row0e * DD + col]
                = acc[im][in][0] + E[(size_t)row0e * DD + col] + h0;
            g_u[(size_t)row0e * DD + col + 1]
                = acc[im][in][1] + E[(size_t)row0e * DD + col + 1] + h1;
            g_u[(size_t)(row0e + 8) * DD + col]
                = acc[im][in][2] + E[(size_t)(row0e + 8) * DD + col] + h0;
            g_u[(size_t)(row0e + 8) * DD + col + 1]
                = acc[im][in][3] + E[(size_t)(row0e + 8) * DD + col + 1] + h1;
        }
    }
}

// ---------------------------------------------------------------------------
// Kernel B: scoring, SINGLE-WAVE layout.
// grid (256, 8) = 2048 CTAs x 128 threads, __launch_bounds__(128, 16):
// 16 CTAs/SM x 148 SMs = 2368 slots >= 2048 -> every CTA co-resident, no
// wave-quantization tail. CTA (b, tc): 8 t-rows; warp w -> rows tc*8+2w,+1.
// ---------------------------------------------------------------------------
__global__ __launch_bounds__(128, 16) void score_kernel(
    const float* __restrict__ E,
    const float* __restrict__ theo,
    const float* __restrict__ cand,
    const float* __restrict__ vb,
    float* __restrict__ out)
{
    const int b    = blockIdx.x;
    const int tc   = blockIdx.y;       // 0..7
    const int tid  = threadIdx.x;
    const int lane = tid & 31;
    const int wid  = tid >> 5;         // 0..3

    __shared__ float u_s[DD];
    __shared__ float red[8];
    __shared__ float s_vb, s_pos;

    // stage u[b] (4 float4 per thread); partial vb-dot; pos-dot on tc==0 only
    float pv = 0.f, pp = 0.f;
    #pragma unroll
    for (int h = 0; h < 4; h++) {
        const int i = h * 512 + tid * 4;
        float4 u4 = *reinterpret_cast<const float4*>(&g_u[(size_t)b * DD + i]);
        *reinterpret_cast<float4*>(&u_s[i]) = u4;
        float4 e4 = *reinterpret_cast<const float4*>(&E[(size_t)b * DD + i]);
        float4 v4 = *reinterpret_cast<const float4*>(&vb[i]);
        pv += e4.x * v4.x + e4.y * v4.y + e4.z * v4.z + e4.w * v4.w;
        if (tc == 0) {
            float4 c4 = *reinterpret_cast<const float4*>(&cand[(size_t)b * DD + i]);
            pp += u4.x * c4.x + u4.y * c4.y + u4.z * c4.z + u4.w * c4.w;
        }
    }
    #pragma unroll
    for (int o = 16; o > 0; o >>= 1) {
        pv += __shfl_xor_sync(0xFFFFFFFFu, pv, o);
        pp += __shfl_xor_sync(0xFFFFFFFFu, pp, o);
    }
    if (lane == 0) { red[wid] = pv; red[4 + wid] = pp; }
    __syncthreads();
    if (tid == 0) {
        float v = red[0] + red[1] + red[2] + red[3];
        float p = red[4] + red[5] + red[6] + red[7];
        s_vb  = v;
        s_pos = p + v;
    }
    __syncthreads();
    const float vbb = s_vb;

    const int t0 = tc * 8 + wid * 2;
    const float4* ra  = reinterpret_cast<const float4*>(&theo[((size_t)b * TT + t0) * DD]);
    const float4* rb  = ra + DD / 4;
    const float4* u4p = reinterpret_cast<const float4*>(u_s);

    float s0 = 0.f, s1 = 0.f;
    #pragma unroll 4
    for (int i = lane; i < DD / 4; i += 32) {
        float4 x = __ldcs(&ra[i]);
        float4 y = __ldcs(&rb[i]);
        float4 u = u4p[i];
        s0 += x.x * u.x + x.y * u.y + x.z * u.z + x.w * u.w;
        s1 += y.x * u.x + y.y * u.y + y.z * u.z + y.w * u.w;
    }
    #pragma unroll
    for (int o = 16; o > 0; o >>= 1) {
        s0 += __shfl_xor_sync(0xFFFFFFFFu, s0, o);
        s1 += __shfl_xor_sync(0xFFFFFFFFu, s1, o);
    }
    if (lane == 0) {
        out[b * (TT + 1) + 1 + t0]     = s0 + vbb;
        out[b * (TT + 1) + 1 + t0 + 1] = s1 + vbb;
    }
    if (tc == 0 && tid == 0) out[b * (TT + 1)] = s_pos;
}

// ---------------------------------------------------------------------------
// launch: 0=experimental [B,D], 1=theoretical [B,T,D], 2=candidate [B,D],
//         3=W [D,D], 4=vb [D], 5=hb [D] ; out fp32 [B, 1+T]
// ---------------------------------------------------------------------------
extern "C" void kernel_launch(void* const* d_in, const int* in_sizes, int n_in,
                              void* d_out, int out_size)
{
    const float* E    = (const float*)d_in[0];
    const float* theo = (const float*)d_in[1];
    const float* cand = (const float*)d_in[2];
    const float* W    = (const float*)d_in[3];
    const float* vb   = (const float*)d_in[4];
    const float* hb   = (const float*)d_in[5];
    float*       out  = (float*)d_out;

    const int npairs = DD * DD / 8 + BB * DD / 8;   // 589824
    convert_kernel<<<npairs / 256, 256>>>(E, W);
    gemm_u_kernel<<<dim3(DD / 64, BB / 64), 256>>>(E, hb);
    score_kernel<<<dim3(BB, 8), 128>>>(E, theo, cand, vb, out);
}